// round 9
// baseline (speedup 1.0000x reference)
#include <cuda_runtime.h>
#include <math.h>

// Problem shapes (fixed by setup_inputs)
#define C_    16
#define H_    256
#define W_    512
#define ND_   32
#define HW_   (H_ * W_)          // 131072
#define NDHW_ (ND_ * HW_)        // 4194304
#define BASELINE_ 0.24f

// Tile: one block = (8 output rows, 32-wide w chunk, all 32 d, 8 of 16 ch)
#define WCH   32
#define HCH   8
#define ROWS_ 51                 // window rows [h0-1, h0+49]; max y1 row = 50
#define RSF4  64                 // row stride in float4 = 2 ch4-planes * 32 wl (0 mod 8)
#define LSZ   (ROWS_ * RSF4)     // 3264 float4
#define SMEM_BYTES (LSZ * 16 + HCH * 8)   // 52224 + 64

// Channel-last copy of y: yT[h][w][c], 64B per pixel, 8 MiB.
__device__ __align__(16) float g_yT[HW_ * C_];

// ---------------------------------------------------------------------------
// Kernel 0: transpose y [C,H,W] -> yT [H,W,C]
// ---------------------------------------------------------------------------
__global__ void transpose_y_kernel(const float* __restrict__ y) {
    int p = blockIdx.x * blockDim.x + threadIdx.x;   // over H*W
    if (p >= HW_) return;
    float4* dst = (float4*)(g_yT + (size_t)p * C_);
#pragma unroll
    for (int c4 = 0; c4 < 4; ++c4) {
        float4 v;
        v.x = __ldg(y + (c4 * 4 + 0) * HW_ + p);
        v.y = __ldg(y + (c4 * 4 + 1) * HW_ + p);
        v.z = __ldg(y + (c4 * 4 + 2) * HW_ + p);
        v.w = __ldg(y + (c4 * 4 + 3) * HW_ + p);
        dst[c4] = v;
    }
}

// ---------------------------------------------------------------------------
// Kernel 1: fused cost volume, channel-split for 3 blocks/SM.
// Block z handles channels [8z, 8z+8) (ch4 planes 2z, 2z+1).
// ---------------------------------------------------------------------------
__global__ __launch_bounds__(512, 3)
void cost_volume_kernel(const float* __restrict__ x,
                        const float* __restrict__ depth,
                        float* __restrict__ out) {
    extern __shared__ float4 L[];              // [ROWS_][2 c2][32 wl]
    float2* thsc = (float2*)(L + LSZ);         // [HCH] {sin, cos}

    int tid  = threadIdx.x;
    int w0   = blockIdx.x * WCH;
    int h0   = blockIdx.y * HCH;
    int chB  = blockIdx.z * 8;                 // first channel of this block
    int ch4B = blockIdx.z * 2;                 // first ch4 plane

    const float PI = 3.14159265358979323846f;
    const float4* yT4 = (const float4*)g_yT;

    // ---- per-band sincos table ----
    if (tid < HCH) {
        float theta = ((float)(h0 + tid) + 0.5f) * (PI / (float)H_) - PI * 0.5f;
        float s, c;
        sincosf(theta, &s, &c);
        thsc[tid] = make_float2(s, c);
    }

    // ---- fill pre-lerped window (STS group = lane%8 -> conflict-free) ----
    for (int k = tid; k < LSZ; k += 512) {
        int wl_low = k & 7;
        int c2     = (k >> 3) & 1;
        int wl     = ((k >> 4) & 3) * 8 + wl_low;
        int r      = k >> 6;
        int gr     = h0 - 1 + r;

        float4 v = make_float4(0.f, 0.f, 0.f, 0.f);
        if (gr >= 0 && gr < H_) {
            int w = w0 + wl;
            // exact reference x math (align_corners=False)
            float gx  = (float)w / ((W_ - 1.0f) * 0.5f) - 1.0f;
            float ix  = ((gx + 1.0f) * (float)W_ - 1.0f) * 0.5f;
            float fx0 = floorf(ix);
            float wx1 = ix - fx0;
            float wx0 = 1.0f - wx1;
            int x0 = (int)fx0;
            int x1 = x0 + 1;
            float a0 = ((x0 >= 0) & (x0 < W_)) ? wx0 : 0.0f;
            float a1 = ((x1 >= 0) & (x1 < W_)) ? wx1 : 0.0f;
            int cx0 = min(max(x0, 0), W_ - 1);
            int cx1 = min(max(x1, 0), W_ - 1);
            const float4* row = yT4 + (size_t)gr * (W_ * 4);
            float4 p0 = row[cx0 * 4 + ch4B + c2];
            float4 p1 = row[cx1 * 4 + ch4B + c2];
            v.x = a0 * p0.x + a1 * p1.x;
            v.y = a0 * p0.y + a1 * p1.y;
            v.z = a0 * p0.z + a1 * p1.z;
            v.w = a0 * p0.w + a1 * p1.w;
        }
        L[r * RSF4 + c2 * WCH + wl] = v;
    }
    __syncthreads();

    int wl    = tid & (WCH - 1);
    int dbase = tid >> 5;                       // 0..15; handles d = dbase, dbase+16
    int w     = w0 + wl;

    int depC0 = (dbase * H_ + h0) * W_ + w;
    float dep_cur = depth[depC0];               // (hh=0, j=0) prefetched

#pragma unroll
    for (int hh = 0; hh < HCH; ++hh) {
        int h = h0 + hh;
        float2 sc   = thsc[hh];
        float theta = ((float)h + 0.5f) * (PI / (float)H_) - PI * 0.5f;

        long ob0 = (long)dbase * HW_ + (long)h * W_ + w;   // d = dbase
        long ob1 = ob0 + 16L * HW_;                        // d = dbase+16

        // ---- reference half: one x load serves both d's ----
        const float* xp = x + chB * HW_ + h * W_ + w;
#pragma unroll
        for (int ch = 0; ch < 8; ++ch) {
            float v = __ldg(xp + ch * HW_);
            out[(long)(chB + ch) * NDHW_ + ob0] = v;
            out[(long)(chB + ch) * NDHW_ + ob1] = v;
        }

#pragma unroll
        for (int j = 0; j < 2; ++j) {
            // software pipeline: prefetch next depth before consuming current
            int lin = hh * 2 + j + 1;
            int nj  = lin & 1;
            int nhh = lin >> 1;
            float dep_next = depth[depC0 + nj * (16 * HW_) +
                                   ((nhh < HCH) ? nhh : 0) * W_];

            float dep = dep_cur;
            float dth = atanf((dep * sc.x + BASELINE_) / (dep * sc.y)) - theta;
            float d_v = dth * ((float)H_ / PI);
            float y_px = (float)h + d_v;        // depth>0, cos(theta)>0 -> finite

            // exact reference y math (align_corners=False)
            float gy  = y_px / ((H_ - 1.0f) * 0.5f) - 1.0f;
            float iy  = ((gy + 1.0f) * (float)H_ - 1.0f) * 0.5f;
            float fy0 = floorf(iy);
            float wy1 = iy - fy0;
            float wy0 = 1.0f - wy1;
            int r0 = (int)fy0 - h0 + 1;          // provably in [0, ROWS_-2]

            const float4* L0 = L + r0 * RSF4 + wl;
            const float4* L1 = L0 + RSF4;

            long ob = (j == 0) ? ob0 : ob1;
            float* op = out + (long)(16 + chB) * NDHW_ + ob;
#pragma unroll
            for (int c2 = 0; c2 < 2; ++c2) {
                float4 u0 = L0[c2 * WCH];
                float4 u1 = L1[c2 * WCH];
                op[(long)(c2 * 4 + 0) * NDHW_] = wy0 * u0.x + wy1 * u1.x;
                op[(long)(c2 * 4 + 1) * NDHW_] = wy0 * u0.y + wy1 * u1.y;
                op[(long)(c2 * 4 + 2) * NDHW_] = wy0 * u0.z + wy1 * u1.z;
                op[(long)(c2 * 4 + 3) * NDHW_] = wy0 * u0.w + wy1 * u1.w;
            }

            dep_cur = dep_next;
        }
    }
}

extern "C" void kernel_launch(void* const* d_in, const int* in_sizes, int n_in,
                              void* d_out, int out_size) {
    const float* x     = (const float*)d_in[0];
    const float* y     = (const float*)d_in[1];
    const float* depth = (const float*)d_in[2];
    float* out = (float*)d_out;

    {
        int total = HW_;
        int threads = 256;
        transpose_y_kernel<<<(total + threads - 1) / threads, threads>>>(y);
    }
    {
        cudaFuncSetAttribute(cost_volume_kernel,
                             cudaFuncAttributeMaxDynamicSharedMemorySize,
                             SMEM_BYTES);
        dim3 grid(W_ / WCH, H_ / HCH, 2);   // (16, 32, 2) = 1024 blocks
        cost_volume_kernel<<<grid, 512, SMEM_BYTES>>>(x, depth, out);
    }
}